// round 9
// baseline (speedup 1.0000x reference)
#include <cuda_runtime.h>
#include <cuda_fp16.h>

// bg:  (1, 4, 32, 32, 32, 16) float32  -> d_in[0]   (c, h, w, d, up)
// gm:  (1, 1, 128, 128, 128)  float32  -> d_in[1]
// out: (1, 4, 128, 128, 128)  float32
//
// Pass 1: x-interp + fp16 channel pack + t-pair duplication:
//         entry X[ih][y][z][t] = {half4 v[t], half4 v[t+1]}.
// Pass 2: per voxel 4 scattered LDG.128. Warps are remapped to 8(id)x4(iw)
//         tiles so all 32 lanes land in ~2x2 grid cells -> ~3x fewer L1
//         gather wavefronts than the linear 32x1 mapping.

#define NVOX      (128 * 128 * 128)      // 2097152
#define XPLANE    (32 * 32 * 16)         // entries (t-indexed) per ih-plane
#define CH_STRIDE (32 * 32 * 32 * 16)    // floats per bg channel
#define SCALE     (31.0f / 127.0f)

__device__ uint4 g_X[128 * XPLANE];      // 33.5 MB scratch (fp16, t-pair dup)

__device__ __forceinline__ unsigned int h2bits(__half2 h) {
    return *reinterpret_cast<unsigned int*>(&h);
}

// ─── Pass 1 ──────────────────────────────────────────────────────────────
__global__ void __launch_bounds__(256) xinterp_kernel(const float* __restrict__ bg) {
    int e2 = blockIdx.x * 256 + threadIdx.x;   // float2 index within plane
    int ih = blockIdx.y;

    float x = fminf((float)ih * SCALE, 31.0f);
    int x0 = (int)x;
    float fx = x - (float)x0;
    int x1 = min(x0 + 1, 31);
    float w0 = 1.0f - fx;

    const float2* __restrict__ bg2 = reinterpret_cast<const float2*>(bg);
    const int CS2 = CH_STRIDE / 2;             // 262144 float2 per channel
    int o0 = x0 * 8192 + e2;
    int o1 = x1 * 8192 + e2;

    float2 a0 = __ldg(bg2 + o0),           a1 = __ldg(bg2 + o1);
    float2 b0 = __ldg(bg2 + CS2 + o0),     b1 = __ldg(bg2 + CS2 + o1);
    float2 c0 = __ldg(bg2 + 2 * CS2 + o0), c1 = __ldg(bg2 + 2 * CS2 + o1);
    float2 d0 = __ldg(bg2 + 3 * CS2 + o0), d1 = __ldg(bg2 + 3 * CS2 + o1);

    float vlx = w0 * a0.x + fx * a1.x,  vhx = w0 * a0.y + fx * a1.y;
    float vly = w0 * b0.x + fx * b1.x,  vhy = w0 * b0.y + fx * b1.y;
    float vlz = w0 * c0.x + fx * c1.x,  vhz = w0 * c0.y + fx * c1.y;
    float vlw = w0 * d0.x + fx * d1.x,  vhw = w0 * d0.y + fx * d1.y;

    unsigned int lo0 = h2bits(__floats2half2_rn(vlx, vly));
    unsigned int lo1 = h2bits(__floats2half2_rn(vlz, vlw));
    unsigned int hi0 = h2bits(__floats2half2_rn(vhx, vhy));
    unsigned int hi1 = h2bits(__floats2half2_rn(vhz, vhw));

    unsigned int n0 = __shfl_down_sync(0xffffffffu, lo0, 1);
    unsigned int n1 = __shfl_down_sync(0xffffffffu, lo1, 1);
    bool last = (e2 & 7) == 7;
    unsigned int q0 = last ? hi0 : n0;
    unsigned int q1 = last ? hi1 : n1;

    int e = ih * XPLANE + 2 * e2;
    g_X[e]     = make_uint4(lo0, lo1, hi0, hi1);
    g_X[e + 1] = make_uint4(hi0, hi1, q0, q1);
}

// ─── Pass 2: tiled warps, 4 gathers ──────────────────────────────────────
__device__ __forceinline__ void acc_corner(uint4 q, float wl, float wh,
                                           float& ax, float& ay, float& az, float& aw) {
    float2 a01 = __half22float2(*reinterpret_cast<__half2*>(&q.x));
    float2 a23 = __half22float2(*reinterpret_cast<__half2*>(&q.y));
    float2 b01 = __half22float2(*reinterpret_cast<__half2*>(&q.z));
    float2 b23 = __half22float2(*reinterpret_cast<__half2*>(&q.w));
    ax = fmaf(wl, a01.x, fmaf(wh, b01.x, ax));
    ay = fmaf(wl, a01.y, fmaf(wh, b01.y, ay));
    az = fmaf(wl, a23.x, fmaf(wh, b23.x, az));
    aw = fmaf(wl, a23.y, fmaf(wh, b23.y, aw));
}

// grid (4, 16, 128) x 256: block covers id-tile 32, iw-tile 8, one ih.
// Warp = 8(id) x 4(iw): lane&7 -> id, lane>>3 -> iw.
__global__ void __launch_bounds__(256) slice_kernel(const float* __restrict__ gm,
                                                    float* __restrict__ out) {
    int lane = threadIdx.x & 31;
    int wrp  = threadIdx.x >> 5;

    int id = (blockIdx.x << 5) + ((wrp & 3) << 3) + (lane & 7);
    int iw = (blockIdx.y << 3) + ((wrp >> 2) << 2) + (lane >> 3);
    int ih = blockIdx.z;

    int idx = (ih << 14) + (iw << 7) + id;

    float y = fminf((float)iw * SCALE, 31.0f);
    float z = fminf((float)id * SCALE, 31.0f);
    float g = gm[idx];
    float t = fminf(fmaxf(g * 15.0f, 0.0f), 15.0f);

    int y0 = (int)y; float fy = y - (float)y0; int y1 = min(y0 + 1, 31);
    int z0 = (int)z; float fz = z - (float)z0; int z1 = min(z0 + 1, 31);
    int t0 = (int)t; float ft = t - (float)t0;

    const uint4* __restrict__ plane = g_X + (ih << 14);

    int b00 = (((y0 << 5) + z0) << 4) + t0;
    int b01 = (((y0 << 5) + z1) << 4) + t0;
    int b10 = (((y1 << 5) + z0) << 4) + t0;
    int b11 = (((y1 << 5) + z1) << 4) + t0;

    uint4 q00 = plane[b00];
    uint4 q01 = plane[b01];
    uint4 q10 = plane[b10];
    uint4 q11 = plane[b11];

    float wy0 = 1.0f - fy, wz0 = 1.0f - fz, wt0 = 1.0f - ft;
    float w00 = wy0 * wz0, w01 = wy0 * fz, w10 = fy * wz0, w11 = fy * fz;

    float ax = 0.f, ay = 0.f, az = 0.f, aw = 0.f;
    acc_corner(q00, w00 * wt0, w00 * ft, ax, ay, az, aw);
    acc_corner(q01, w01 * wt0, w01 * ft, ax, ay, az, aw);
    acc_corner(q10, w10 * wt0, w10 * ft, ax, ay, az, aw);
    acc_corner(q11, w11 * wt0, w11 * ft, ax, ay, az, aw);

    out[idx]            = ax;
    out[NVOX + idx]     = ay;
    out[2 * NVOX + idx] = az;
    out[3 * NVOX + idx] = aw;
}

extern "C" void kernel_launch(void* const* d_in, const int* in_sizes, int n_in,
                              void* d_out, int out_size) {
    const float* bg = (const float*)d_in[0];
    const float* gm = (const float*)d_in[1];
    float* out = (float*)d_out;

    xinterp_kernel<<<dim3(32, 128), 256>>>(bg);
    slice_kernel<<<dim3(4, 16, 128), 256>>>(gm, out);
}

// round 17
// speedup vs baseline: 1.3515x; 1.3515x over previous
#include <cuda_runtime.h>
#include <cuda_fp16.h>

// bg:  (1, 4, 32, 32, 32, 16) float32  -> d_in[0]   (c, h, w, d, up)
// gm:  (1, 1, 128, 128, 128)  float32  -> d_in[1]
// out: (1, 4, 128, 128, 128)  float32
//
// Pass 1: x-interp along ih + fp16 channel pack. Entry X[ih][y][z][t] =
//         {half4 v[t]} (8 B). No t-duplication -> X is 16.8 MB (half of R6),
//         halving pass-1's write bandwidth. A (y,z) cell = 16t x 8B = 128 B
//         = exactly one L1 line.
// Pass 2: linear voxel mapping (R6 — the R9 warp-tile remap regressed).
//         Per voxel 8 x 8B gathers (2 t-planes x 4 (y,z) corners); the two
//         t entries of a corner live in the SAME 128B line.

#define NVOX      (128 * 128 * 128)      // 2097152
#define XPLANE    (32 * 32 * 16)         // entries per ih-plane
#define CH_STRIDE (32 * 32 * 32 * 16)    // floats per bg channel
#define SCALE     (31.0f / 127.0f)

__device__ uint2 g_X[128 * XPLANE];      // 16.8 MB scratch (fp16, no dup)

__device__ __forceinline__ unsigned int h2bits(__half2 h) {
    return *reinterpret_cast<unsigned int*>(&h);
}

// ─── Pass 1: x-interp + fp16 pack, one thread per t-pair ─────────────────
// grid (32, 128) x 256: blockIdx.y = ih, e2 = float2 index over (y,z,t/2).
// Each thread writes entries t=2k and t=2k+1 as ONE aligned 16B store.
__global__ void __launch_bounds__(256) xinterp_kernel(const float* __restrict__ bg) {
    int e2 = blockIdx.x * 256 + threadIdx.x;   // 0..8191 within plane
    int ih = blockIdx.y;

    float x = fminf((float)ih * SCALE, 31.0f);
    int x0 = (int)x;
    float fx = x - (float)x0;
    int x1 = min(x0 + 1, 31);
    float w0 = 1.0f - fx;

    const float2* __restrict__ bg2 = reinterpret_cast<const float2*>(bg);
    const int CS2 = CH_STRIDE / 2;             // 262144 float2 per channel
    int o0 = x0 * 8192 + e2;
    int o1 = x1 * 8192 + e2;

    float2 a0 = __ldg(bg2 + o0),           a1 = __ldg(bg2 + o1);
    float2 b0 = __ldg(bg2 + CS2 + o0),     b1 = __ldg(bg2 + CS2 + o1);
    float2 c0 = __ldg(bg2 + 2 * CS2 + o0), c1 = __ldg(bg2 + 2 * CS2 + o1);
    float2 d0 = __ldg(bg2 + 3 * CS2 + o0), d1 = __ldg(bg2 + 3 * CS2 + o1);

    // v at t=2k (lo) and t=2k+1 (hi), 4 channels each
    float vlx = w0 * a0.x + fx * a1.x,  vhx = w0 * a0.y + fx * a1.y;
    float vly = w0 * b0.x + fx * b1.x,  vhy = w0 * b0.y + fx * b1.y;
    float vlz = w0 * c0.x + fx * c1.x,  vhz = w0 * c0.y + fx * c1.y;
    float vlw = w0 * d0.x + fx * d1.x,  vhw = w0 * d0.y + fx * d1.y;

    unsigned int lo0 = h2bits(__floats2half2_rn(vlx, vly));
    unsigned int lo1 = h2bits(__floats2half2_rn(vlz, vlw));
    unsigned int hi0 = h2bits(__floats2half2_rn(vhx, vhy));
    unsigned int hi1 = h2bits(__floats2half2_rn(vhz, vhw));

    reinterpret_cast<uint4*>(g_X)[ih * 8192 + e2] = make_uint4(lo0, lo1, hi0, hi1);
}

// ─── Pass 2: linear mapping, 8 x 8B gathers ──────────────────────────────
__device__ __forceinline__ void acc_corner(uint2 ql, uint2 qh, float wl, float wh,
                                           float& ax, float& ay, float& az, float& aw) {
    float2 a01 = __half22float2(*reinterpret_cast<__half2*>(&ql.x));
    float2 a23 = __half22float2(*reinterpret_cast<__half2*>(&ql.y));
    float2 b01 = __half22float2(*reinterpret_cast<__half2*>(&qh.x));
    float2 b23 = __half22float2(*reinterpret_cast<__half2*>(&qh.y));
    ax = fmaf(wl, a01.x, fmaf(wh, b01.x, ax));
    ay = fmaf(wl, a01.y, fmaf(wh, b01.y, ay));
    az = fmaf(wl, a23.x, fmaf(wh, b23.x, az));
    aw = fmaf(wl, a23.y, fmaf(wh, b23.y, aw));
}

__global__ void __launch_bounds__(256) slice_kernel(const float* __restrict__ gm,
                                                    float* __restrict__ out) {
    int idx = blockIdx.x * 256 + threadIdx.x;

    int id = idx & 127;
    int iw = (idx >> 7) & 127;
    int ih = idx >> 14;

    float y = fminf((float)iw * SCALE, 31.0f);
    float z = fminf((float)id * SCALE, 31.0f);
    float g = gm[idx];
    float t = fminf(fmaxf(g * 15.0f, 0.0f), 15.0f);

    int y0 = (int)y; float fy = y - (float)y0; int y1 = min(y0 + 1, 31);
    int z0 = (int)z; float fz = z - (float)z0; int z1 = min(z0 + 1, 31);
    int t0 = (int)t; float ft = t - (float)t0; int t1 = min(t0 + 1, 15);

    const uint2* __restrict__ plane = g_X + (ih << 14);

    int b00 = ((y0 << 5) + z0) << 4;
    int b01 = ((y0 << 5) + z1) << 4;
    int b10 = ((y1 << 5) + z0) << 4;
    int b11 = ((y1 << 5) + z1) << 4;

    // 8 loads issued up front; each corner's t0/t1 hit the same 128B line.
    uint2 q00l = plane[b00 + t0], q00h = plane[b00 + t1];
    uint2 q01l = plane[b01 + t0], q01h = plane[b01 + t1];
    uint2 q10l = plane[b10 + t0], q10h = plane[b10 + t1];
    uint2 q11l = plane[b11 + t0], q11h = plane[b11 + t1];

    float wy0 = 1.0f - fy, wz0 = 1.0f - fz, wt0 = 1.0f - ft;
    float w00 = wy0 * wz0, w01 = wy0 * fz, w10 = fy * wz0, w11 = fy * fz;

    float ax = 0.f, ay = 0.f, az = 0.f, aw = 0.f;
    acc_corner(q00l, q00h, w00 * wt0, w00 * ft, ax, ay, az, aw);
    acc_corner(q01l, q01h, w01 * wt0, w01 * ft, ax, ay, az, aw);
    acc_corner(q10l, q10h, w10 * wt0, w10 * ft, ax, ay, az, aw);
    acc_corner(q11l, q11h, w11 * wt0, w11 * ft, ax, ay, az, aw);

    out[idx]            = ax;
    out[NVOX + idx]     = ay;
    out[2 * NVOX + idx] = az;
    out[3 * NVOX + idx] = aw;
}

extern "C" void kernel_launch(void* const* d_in, const int* in_sizes, int n_in,
                              void* d_out, int out_size) {
    const float* bg = (const float*)d_in[0];
    const float* gm = (const float*)d_in[1];
    float* out = (float*)d_out;

    xinterp_kernel<<<dim3(32, 128), 256>>>(bg);
    slice_kernel<<<NVOX / 256, 256>>>(gm, out);
}